// round 6
// baseline (speedup 1.0000x reference)
#include <cuda_runtime.h>

// TemporalTransformerBlock, fp32 + Blackwell packed f32x2.
// 65536 seqs, T=24, D=16, NH=4, HD=4, DFF=64, 2 layers.
// Geometry: 96 threads/block = 16 seqs x 6 threads; 4 tokens/thread.
// Weights prepacked into __device__ global by a prep kernel (Q rows
// pre-scaled by 0.5*log2e, W2 transposed); read via uniform LDG.
// Smem holds only K/V (SoA per sequence) -> 4 blocks/SM.

namespace {
constexpr int HW   = 256 * 256;
constexpr int T    = 24;
constexpr int D    = 16;
constexpr int NH   = 4;
constexpr int DFF  = 64;
constexpr int NL   = 2;
constexpr int S    = 16;           // sequences per block
constexpr int TPS  = 6;            // threads per sequence (4 tokens each)
constexpr int NT   = S * TPS;      // 96 threads

constexpr float QSCALE = 0.7213475204444817f;   // 0.5 * log2(e)

// packed-weight array offsets (floats)
constexpr int OFF_WQKV = 0;        // 2*48*16 = 1536 (Q rows pre-scaled)
constexpr int OFF_BQKV = 1536;     // 96
constexpr int OFF_WO   = 1632;     // 512
constexpr int OFF_BO   = 2144;     // 32
constexpr int OFF_W1   = 2176;     // 2048
constexpr int OFF_B1   = 4224;     // 128
constexpr int OFF_W2T  = 4352;     // 2048  (W2 transposed [l][o][d])
constexpr int OFF_B2   = 6400;     // 32
constexpr int OFF_LN1W = 6432;
constexpr int OFF_LN1B = 6464;
constexpr int OFF_LN2W = 6496;
constexpr int OFF_LN2B = 6528;
constexpr int OFF_WIN  = 6560;
constexpr int OFF_BIN  = 6576;
constexpr int OFF_WOUT = 6592;
constexpr int OFF_BOUT = 6608;
constexpr int WPACK_FLOATS = 6656;

// K/V smem: SoA per sequence, row = head*4+d (16 rows), col = token.
constexpr int SROW = 24;                       // row stride (floats, even)
constexpr int KSEQ = 16 * SROW + 4;            // 388: seq bases 2 u64-banks apart
constexpr int OFF_K = 0;
constexpr int OFF_V = S * KSEQ;                // 6208
constexpr int SMEM_FLOATS = 2 * S * KSEQ;      // 12416
constexpr int SMEM_BYTES  = SMEM_FLOATS * 4;   // 49664
}

__device__ float g_wpack[WPACK_FLOATS];

using u64 = unsigned long long;

__device__ __forceinline__ u64 pk(float lo, float hi) {
    u64 r; asm("mov.b64 %0, {%1, %2};" : "=l"(r) : "f"(lo), "f"(hi)); return r;
}
__device__ __forceinline__ void unpk(u64 p, float& lo, float& hi) {
    asm("mov.b64 {%0, %1}, %2;" : "=f"(lo), "=f"(hi) : "l"(p));
}
__device__ __forceinline__ u64 pfma(u64 a, u64 b, u64 c) {
    u64 d; asm("fma.rn.f32x2 %0, %1, %2, %3;" : "=l"(d) : "l"(a), "l"(b), "l"(c));
    return d;
}
__device__ __forceinline__ u64 padd(u64 a, u64 b) {
    u64 d; asm("add.rn.f32x2 %0, %1, %2;" : "=l"(d) : "l"(a), "l"(b)); return d;
}
__device__ __forceinline__ u64 pmul(u64 a, u64 b) {
    u64 d; asm("mul.rn.f32x2 %0, %1, %2;" : "=l"(d) : "l"(a), "l"(b)); return d;
}
__device__ __forceinline__ float hadd(u64 p) {
    float lo, hi; unpk(p, lo, hi); return lo + hi;
}
__device__ __forceinline__ float ex2f(float x) {
    float r; asm("ex2.approx.f32 %0, %1;" : "=f"(r) : "f"(x)); return r;
}
__device__ __forceinline__ float rcpf(float x) {
    float r; asm("rcp.approx.f32 %0, %1;" : "=f"(r) : "f"(x)); return r;
}

// 4-token dot against one global weight row (LDG.128 x4, shared by 4 tokens).
__device__ __forceinline__ void dotg16x4(const u64* a0, const u64* a1,
                                         const u64* a2, const u64* a3,
                                         const float* __restrict__ w, float bias,
                                         float& r0, float& r1, float& r2, float& r3) {
    const ulonglong2* w2 = reinterpret_cast<const ulonglong2*>(w);
    u64 c0 = 0ull, c1 = 0ull, c2 = 0ull, c3 = 0ull;
#pragma unroll
    for (int c = 0; c < 4; c++) {
        ulonglong2 wv = w2[c];
        c0 = pfma(a0[2*c],   wv.x, c0);
        c1 = pfma(a1[2*c],   wv.x, c1);
        c2 = pfma(a2[2*c],   wv.x, c2);
        c3 = pfma(a3[2*c],   wv.x, c3);
        c0 = pfma(a0[2*c+1], wv.y, c0);
        c1 = pfma(a1[2*c+1], wv.y, c1);
        c2 = pfma(a2[2*c+1], wv.y, c2);
        c3 = pfma(a3[2*c+1], wv.y, c3);
    }
    r0 = bias + hadd(c0); r1 = bias + hadd(c1);
    r2 = bias + hadd(c2); r3 = bias + hadd(c3);
}

// 2-token dot against one global weight row.
__device__ __forceinline__ void dotg16x2(const u64* a0, const u64* a1,
                                         const float* __restrict__ w, float bias,
                                         float& r0, float& r1) {
    const ulonglong2* w2 = reinterpret_cast<const ulonglong2*>(w);
    u64 c0 = 0ull, c1 = 0ull;
#pragma unroll
    for (int c = 0; c < 4; c++) {
        ulonglong2 wv = w2[c];
        c0 = pfma(a0[2*c],   wv.x, c0);
        c1 = pfma(a1[2*c],   wv.x, c1);
        c0 = pfma(a0[2*c+1], wv.y, c0);
        c1 = pfma(a1[2*c+1], wv.y, c1);
    }
    r0 = bias + hadd(c0);
    r1 = bias + hadd(c1);
}

// packed LayerNorm over 8 pairs; gamma/beta from global.
__device__ __forceinline__ void ln16p(const u64* y, const float* __restrict__ g,
                                      const float* __restrict__ b, u64* o) {
    u64 s01 = padd(padd(y[0], y[1]), padd(y[2], y[3]));
    u64 s23 = padd(padd(y[4], y[5]), padd(y[6], y[7]));
    float mu = hadd(padd(s01, s23)) * 0.0625f;
    u64 nmu = pk(-mu, -mu);
    u64 c[8];
    u64 v2 = 0ull;
#pragma unroll
    for (int dp = 0; dp < 8; dp++) {
        c[dp] = padd(y[dp], nmu);
        v2 = pfma(c[dp], c[dp], v2);
    }
    float rs = rsqrtf(fmaf(hadd(v2), 0.0625f, 1e-5f));
    u64 rs2 = pk(rs, rs);
    const ulonglong2* g2 = reinterpret_cast<const ulonglong2*>(g);
    const ulonglong2* b2 = reinterpret_cast<const ulonglong2*>(b);
#pragma unroll
    for (int q = 0; q < 4; q++) {
        ulonglong2 gv = g2[q], bv = b2[q];
        o[2*q]   = pfma(pmul(c[2*q],   rs2), gv.x, bv.x);
        o[2*q+1] = pfma(pmul(c[2*q+1], rs2), gv.y, bv.y);
    }
}

// ---- prep kernel: pack/transform all weights into g_wpack ----
__global__ void prep_kernel(const float* __restrict__ Wqkv, const float* __restrict__ bqkv,
                            const float* __restrict__ Wo,   const float* __restrict__ bo,
                            const float* __restrict__ W1,   const float* __restrict__ b1,
                            const float* __restrict__ W2,   const float* __restrict__ b2,
                            const float* __restrict__ ln1w, const float* __restrict__ ln1b,
                            const float* __restrict__ ln2w, const float* __restrict__ ln2b,
                            const float* __restrict__ Win,  const float* __restrict__ binp,
                            const float* __restrict__ Wout, const float* __restrict__ bout) {
    const int tid = threadIdx.x;
    const int nt = blockDim.x;
    for (int i = tid; i < 1536; i += nt) {
        float w = Wqkv[i];
        if (((i % 768) >> 4) < 16) w *= QSCALE;   // Q rows of each layer
        g_wpack[OFF_WQKV + i] = w;
    }
    for (int i = tid; i < 96; i += nt) {
        float w = bqkv[i];
        if ((i % 48) < 16) w *= QSCALE;
        g_wpack[OFF_BQKV + i] = w;
    }
    for (int i = tid; i <  512; i += nt) g_wpack[OFF_WO   + i] = Wo[i];
    for (int i = tid; i <   32; i += nt) g_wpack[OFF_BO   + i] = bo[i];
    for (int i = tid; i < 2048; i += nt) g_wpack[OFF_W1   + i] = W1[i];
    for (int i = tid; i <  128; i += nt) g_wpack[OFF_B1   + i] = b1[i];
    for (int i = tid; i < 2048; i += nt) {      // W2 [l][d][o] -> [l][o][d]
        int l = i >> 10, rem = i & 1023, o = rem >> 4, d = rem & 15;
        g_wpack[OFF_W2T + i] = W2[l * 1024 + d * 64 + o];
    }
    for (int i = tid; i <   32; i += nt) g_wpack[OFF_B2   + i] = b2[i];
    for (int i = tid; i <   32; i += nt) g_wpack[OFF_LN1W + i] = ln1w[i];
    for (int i = tid; i <   32; i += nt) g_wpack[OFF_LN1B + i] = ln1b[i];
    for (int i = tid; i <   32; i += nt) g_wpack[OFF_LN2W + i] = ln2w[i];
    for (int i = tid; i <   32; i += nt) g_wpack[OFF_LN2B + i] = ln2b[i];
    for (int i = tid; i <   16; i += nt) g_wpack[OFF_WIN  + i] = Win[i];
    for (int i = tid; i <   16; i += nt) g_wpack[OFF_BIN  + i] = binp[i];
    for (int i = tid; i <   16; i += nt) g_wpack[OFF_WOUT + i] = Wout[i];
    if (tid == 0) g_wpack[OFF_BOUT] = bout[0];
}

__global__ __launch_bounds__(NT, 4)
void ttb_kernel(const float* __restrict__ x, float* __restrict__ out) {
    extern __shared__ float sm[];
    const int tid = threadIdx.x;
    const int sl = tid / TPS;
    const int r  = tid % TPS;
    const int n  = blockIdx.x * S + sl;
    const int t0 = 4 * r;                 // tokens t0 .. t0+3

    const float* __restrict__ w = g_wpack;

    // ---- input projection: hp[j] = x[t0+j]*Win + bin, as 8 d-pairs ----
    u64 hp[4][8];
    {
        const ulonglong2* w2 = reinterpret_cast<const ulonglong2*>(w + OFF_WIN);
        const ulonglong2* b2 = reinterpret_cast<const ulonglong2*>(w + OFF_BIN);
#pragma unroll
        for (int j = 0; j < 4; j++) {
            float xv = x[(t0 + j) * HW + n];
            u64 xp = pk(xv, xv);
#pragma unroll
            for (int c = 0; c < 4; c++) {
                ulonglong2 wv = w2[c], bv = b2[c];
                hp[j][2*c]   = pfma(xp, wv.x, bv.x);
                hp[j][2*c+1] = pfma(xp, wv.y, bv.y);
            }
        }
    }

    float* ksh = &sm[OFF_K + sl * KSEQ];
    float* vsh = &sm[OFF_V + sl * KSEQ];

#pragma unroll 1
    for (int l = 0; l < NL; l++) {
        const float* wqkv = w + OFF_WQKV + l * 768;
        const float* bq   = w + OFF_BQKV + l * 48;
        const float* wo   = w + OFF_WO   + l * 256;
        const float* bov  = w + OFF_BO   + l * 16;
        const float* w1   = w + OFF_W1   + l * 1024;
        const float* b1v  = w + OFF_B1   + l * 64;
        const float* w2t  = w + OFF_W2T  + l * 1024;
        const float* b2v  = w + OFF_B2   + l * 16;
        const float* g1w  = w + OFF_LN1W + l * 16;
        const float* g1b  = w + OFF_LN1B + l * 16;
        const float* g2w  = w + OFF_LN2W + l * 16;
        const float* g2b  = w + OFF_LN2B + l * 16;

        // ---- K,V projection -> SoA shared (row = head*4+d, col = token) ----
#pragma unroll 4
        for (int o = 0; o < D; o++) {       // K rows
            float r0, r1, r2, r3;
            dotg16x4(hp[0], hp[1], hp[2], hp[3],
                     wqkv + (D + o) * D, bq[D + o], r0, r1, r2, r3);
            *reinterpret_cast<u64*>(&ksh[o * SROW + t0])     = pk(r0, r1);
            *reinterpret_cast<u64*>(&ksh[o * SROW + t0 + 2]) = pk(r2, r3);
        }
#pragma unroll 4
        for (int o = 0; o < D; o++) {       // V rows
            float r0, r1, r2, r3;
            dotg16x4(hp[0], hp[1], hp[2], hp[3],
                     wqkv + (2 * D + o) * D, bq[2 * D + o], r0, r1, r2, r3);
            *reinterpret_cast<u64*>(&vsh[o * SROW + t0])     = pk(r0, r1);
            *reinterpret_cast<u64*>(&vsh[o * SROW + t0 + 2]) = pk(r2, r3);
        }
        __syncthreads();

        // ---- attention + Wo + LN1, processed per token-pair ----
#pragma unroll
        for (int p = 0; p < 2; p++) {
            u64* hA = hp[2*p];
            u64* hB = hp[2*p + 1];
            u64 cpa[8], cpb[8];               // ctx for the two tokens
#pragma unroll
            for (int hd = 0; hd < NH; hd++) {
                // q (Q weights pre-scaled -> logits in log2 units)
                float q00, q01, q02, q03, q10, q11, q12, q13;
                dotg16x2(hA, hB, wqkv + (4*hd + 0) * D, bq[4*hd + 0], q00, q10);
                dotg16x2(hA, hB, wqkv + (4*hd + 1) * D, bq[4*hd + 1], q01, q11);
                dotg16x2(hA, hB, wqkv + (4*hd + 2) * D, bq[4*hd + 2], q02, q12);
                dotg16x2(hA, hB, wqkv + (4*hd + 3) * D, bq[4*hd + 3], q03, q13);
                const float* kb = ksh + hd * (4 * SROW);
                const float* vb = vsh + hd * (4 * SROW);
#pragma unroll
                for (int j = 0; j < 2; j++) {
                    u64 qp0 = pk(j ? q10 : q00, j ? q10 : q00);
                    u64 qp1 = pk(j ? q11 : q01, j ? q11 : q01);
                    u64 qp2 = pk(j ? q12 : q02, j ? q12 : q02);
                    u64 qp3 = pk(j ? q13 : q03, j ? q13 : q03);
                    u64 lg[T / 2];
#pragma unroll
                    for (int sp = 0; sp < T / 2; sp++) {
                        u64 k0 = *reinterpret_cast<const u64*>(kb + 2 * sp);
                        u64 k1 = *reinterpret_cast<const u64*>(kb + SROW + 2 * sp);
                        u64 k2 = *reinterpret_cast<const u64*>(kb + 2 * SROW + 2 * sp);
                        u64 k3 = *reinterpret_cast<const u64*>(kb + 3 * SROW + 2 * sp);
                        lg[sp] = pfma(qp0, k0, pfma(qp1, k1, pfma(qp2, k2, pmul(qp3, k3))));
                    }
                    // softmax in base-2, no max-subtraction (tiny logits)
                    u64 s2 = 0ull;
#pragma unroll
                    for (int sp = 0; sp < T / 2; sp++) {
                        float a, b; unpk(lg[sp], a, b);
                        u64 e = pk(ex2f(a), ex2f(b));
                        lg[sp] = e;
                        s2 = padd(s2, e);
                    }
                    float inv = rcpf(hadd(s2));
                    u64 c0 = 0ull, c1 = 0ull, c2 = 0ull, c3 = 0ull;
#pragma unroll
                    for (int sp = 0; sp < T / 2; sp++) {
                        u64 v0 = *reinterpret_cast<const u64*>(vb + 2 * sp);
                        u64 v1 = *reinterpret_cast<const u64*>(vb + SROW + 2 * sp);
                        u64 v2 = *reinterpret_cast<const u64*>(vb + 2 * SROW + 2 * sp);
                        u64 v3 = *reinterpret_cast<const u64*>(vb + 3 * SROW + 2 * sp);
                        c0 = pfma(lg[sp], v0, c0);
                        c1 = pfma(lg[sp], v1, c1);
                        c2 = pfma(lg[sp], v2, c2);
                        c3 = pfma(lg[sp], v3, c3);
                    }
                    u64 pa = pk(hadd(c0) * inv, hadd(c1) * inv);
                    u64 pb = pk(hadd(c2) * inv, hadd(c3) * inv);
                    if (j == 0) { cpa[2*hd] = pa; cpa[2*hd+1] = pb; }
                    else        { cpb[2*hd] = pa; cpb[2*hd+1] = pb; }
                }
            }
            // Wo + residual + LN1 for this pair
            u64 y0[8], y1[8];
#pragma unroll
            for (int dp = 0; dp < 8; dp++) {
                float a0, a1, b0, b1_;
                dotg16x2(cpa, cpb, wo + (2*dp) * D,     bov[2*dp],     a0, a1);
                dotg16x2(cpa, cpb, wo + (2*dp + 1) * D, bov[2*dp + 1], b0, b1_);
                y0[dp] = padd(hA[dp], pk(a0, b0));
                y1[dp] = padd(hB[dp], pk(a1, b1_));
            }
            ln16p(y0, g1w, g1b, hA);
            ln16p(y1, g1w, g1b, hB);
        }

        // ---- FFN over 4 tokens (weight rows shared by all 4) ----
        {
            u64 f[4][8];
            {
                const ulonglong2* bb = reinterpret_cast<const ulonglong2*>(b2v);
#pragma unroll
                for (int q = 0; q < 4; q++) {
                    ulonglong2 bv = bb[q];
#pragma unroll
                    for (int j = 0; j < 4; j++) { f[j][2*q] = bv.x; f[j][2*q+1] = bv.y; }
                }
            }
#pragma unroll 4
            for (int o = 0; o < DFF; o++) {
                float u0, u1, u2, u3;
                dotg16x4(hp[0], hp[1], hp[2], hp[3], w1 + o * D, b1v[o],
                         u0, u1, u2, u3);
                u0 = fmaxf(u0, 0.f); u1 = fmaxf(u1, 0.f);
                u2 = fmaxf(u2, 0.f); u3 = fmaxf(u3, 0.f);
                u64 up0 = pk(u0, u0), up1 = pk(u1, u1);
                u64 up2 = pk(u2, u2), up3 = pk(u3, u3);
                const ulonglong2* wr = reinterpret_cast<const ulonglong2*>(w2t + o * D);
#pragma unroll
                for (int c = 0; c < 4; c++) {
                    ulonglong2 wv = wr[c];
                    f[0][2*c]   = pfma(up0, wv.x, f[0][2*c]);
                    f[0][2*c+1] = pfma(up0, wv.y, f[0][2*c+1]);
                    f[1][2*c]   = pfma(up1, wv.x, f[1][2*c]);
                    f[1][2*c+1] = pfma(up1, wv.y, f[1][2*c+1]);
                    f[2][2*c]   = pfma(up2, wv.x, f[2][2*c]);
                    f[2][2*c+1] = pfma(up2, wv.y, f[2][2*c+1]);
                    f[3][2*c]   = pfma(up3, wv.x, f[3][2*c]);
                    f[3][2*c+1] = pfma(up3, wv.y, f[3][2*c+1]);
                }
            }
#pragma unroll
            for (int j = 0; j < 4; j++) {
                u64 y[8];
#pragma unroll
                for (int dp = 0; dp < 8; dp++) y[dp] = padd(hp[j][dp], f[j][dp]);
                ln16p(y, g2w, g2b, hp[j]);
            }
        }
        __syncthreads();   // K/V reuse by next layer
    }

    // ---- output projection ----
    {
        const ulonglong2* w2 = reinterpret_cast<const ulonglong2*>(w + OFF_WOUT);
        float bo_ = w[OFF_BOUT];
#pragma unroll
        for (int j = 0; j < 4; j++) {
            u64 acc = 0ull;
#pragma unroll
            for (int c = 0; c < 4; c++) {
                ulonglong2 wv = w2[c];
                acc = pfma(hp[j][2*c],   wv.x, acc);
                acc = pfma(hp[j][2*c+1], wv.y, acc);
            }
            out[(t0 + j) * HW + n] = hadd(acc) + bo_;
        }
    }
}

extern "C" void kernel_launch(void* const* d_in, const int* in_sizes, int n_in,
                              void* d_out, int out_size) {
    (void)in_sizes; (void)n_in; (void)out_size;
    prep_kernel<<<1, 192>>>(
        (const float*)d_in[3],  (const float*)d_in[4],   // Wqkv, bqkv
        (const float*)d_in[5],  (const float*)d_in[6],   // Wo, bo
        (const float*)d_in[9],  (const float*)d_in[10],  // W1, b1
        (const float*)d_in[11], (const float*)d_in[12],  // W2, b2
        (const float*)d_in[7],  (const float*)d_in[8],   // ln1w, ln1b
        (const float*)d_in[13], (const float*)d_in[14],  // ln2w, ln2b
        (const float*)d_in[1],  (const float*)d_in[2],   // Win, bin
        (const float*)d_in[15], (const float*)d_in[16]); // Wout, bout
    cudaFuncSetAttribute(ttb_kernel, cudaFuncAttributeMaxDynamicSharedMemorySize,
                         SMEM_BYTES);
    ttb_kernel<<<HW / S, NT, SMEM_BYTES>>>((const float*)d_in[0], (float*)d_out);
}

// round 11
// speedup vs baseline: 2.9533x; 2.9533x over previous
#include <cuda_runtime.h>

// TemporalTransformerBlock, fp32 + Blackwell packed f32x2.
// 65536 seqs, T=24, D=16, NH=4, HD=4, DFF=64, 2 layers.
// 12 threads/sequence, 2 tokens/thread; weights in smem (broadcast LDS);
// K/V SoA in smem; Q stashed in per-thread smem so attention shares
// K/V loads across both tokens without blowing the 170-reg cap.

namespace {
constexpr int HW   = 256 * 256;
constexpr int T    = 24;
constexpr int D    = 16;
constexpr int NH   = 4;
constexpr int DFF  = 64;
constexpr int NL   = 2;
constexpr int S    = 16;          // sequences per block
constexpr int TPS  = 12;          // threads per sequence
constexpr int NT   = S * TPS;     // 192

constexpr float QSCALE = 0.7213475204444817f;   // 0.5 * log2(e)

// shared-memory float offsets
constexpr int OFF_WQKV = 0;                     // 1536
constexpr int OFF_BQKV = 1536;                  // 96
constexpr int OFF_WO   = 1632;                  // 512
constexpr int OFF_BO   = 2144;                  // 32
constexpr int OFF_W1   = 2176;                  // 2048
constexpr int OFF_B1   = 4224;                  // 128
constexpr int OFF_W2T  = 4352;                  // 2048 (W2 transposed [o][d])
constexpr int OFF_B2   = 6400;                  // 32
constexpr int OFF_LN1W = 6432;                  // 32
constexpr int OFF_LN1B = 6464;                  // 32
constexpr int OFF_LN2W = 6496;                  // 32
constexpr int OFF_LN2B = 6528;                  // 32
constexpr int OFF_WIN  = 6560;                  // 16
constexpr int OFF_BIN  = 6576;                  // 16
constexpr int OFF_WOUT = 6592;                  // 16
constexpr int OFF_BOUT = 6608;                  // 1 (+3 pad)
constexpr int OFF_XS   = 6612;                  // 24*17 = 408

// K/V SoA per sequence: row = head*4+d (16 rows), column = token s.
constexpr int SROW = 26;                        // padded row stride (even)
constexpr int KSEQ = 16 * SROW + 8;             // 424
constexpr int OFF_K = 7020;
constexpr int OFF_V = OFF_K + S * KSEQ;         // 13804
// per-thread Q stash: 32 floats used, stride 34 (odd 8B-bank step -> no conflict)
constexpr int OFF_HS = OFF_V + S * KSEQ;        // 20588
constexpr int HS_STRIDE = 34;
constexpr int SMEM_FLOATS = OFF_HS + NT * HS_STRIDE;   // 27116
constexpr int SMEM_BYTES  = SMEM_FLOATS * 4;           // 108464
}

using u64 = unsigned long long;

__device__ __forceinline__ u64 pk(float lo, float hi) {
    u64 r; asm("mov.b64 %0, {%1, %2};" : "=l"(r) : "f"(lo), "f"(hi)); return r;
}
__device__ __forceinline__ void unpk(u64 p, float& lo, float& hi) {
    asm("mov.b64 {%0, %1}, %2;" : "=f"(lo), "=f"(hi) : "l"(p));
}
__device__ __forceinline__ u64 pfma(u64 a, u64 b, u64 c) {
    u64 d; asm("fma.rn.f32x2 %0, %1, %2, %3;" : "=l"(d) : "l"(a), "l"(b), "l"(c));
    return d;
}
__device__ __forceinline__ u64 padd(u64 a, u64 b) {
    u64 d; asm("add.rn.f32x2 %0, %1, %2;" : "=l"(d) : "l"(a), "l"(b)); return d;
}
__device__ __forceinline__ u64 pmul(u64 a, u64 b) {
    u64 d; asm("mul.rn.f32x2 %0, %1, %2;" : "=l"(d) : "l"(a), "l"(b)); return d;
}
__device__ __forceinline__ float hadd(u64 p) {
    float lo, hi; unpk(p, lo, hi); return lo + hi;
}
__device__ __forceinline__ float ex2f(float x) {
    float r; asm("ex2.approx.f32 %0, %1;" : "=f"(r) : "f"(x)); return r;
}
__device__ __forceinline__ float rcpf(float x) {
    float r; asm("rcp.approx.f32 %0, %1;" : "=f"(r) : "f"(x)); return r;
}

// two 16-dots (both tokens) against one shared weight row (LDS.128 broadcast).
__device__ __forceinline__ void dot16x2p(const u64* a0, const u64* a1,
                                         const float* w, float bias,
                                         float& r0, float& r1) {
    const ulonglong2* w2 = reinterpret_cast<const ulonglong2*>(w);
    u64 acc0 = 0ull, acc1 = 0ull;
#pragma unroll
    for (int c = 0; c < 4; c++) {
        ulonglong2 wv = w2[c];
        acc0 = pfma(a0[2*c],   wv.x, acc0);
        acc1 = pfma(a1[2*c],   wv.x, acc1);
        acc0 = pfma(a0[2*c+1], wv.y, acc0);
        acc1 = pfma(a1[2*c+1], wv.y, acc1);
    }
    r0 = bias + hadd(acc0);
    r1 = bias + hadd(acc1);
}

// packed LayerNorm over 8 pairs (one token)
__device__ __forceinline__ void ln16p(const u64* y, const float* g,
                                      const float* b, u64* o) {
    u64 s01 = padd(padd(y[0], y[1]), padd(y[2], y[3]));
    u64 s23 = padd(padd(y[4], y[5]), padd(y[6], y[7]));
    float mu = hadd(padd(s01, s23)) * 0.0625f;
    u64 nmu = pk(-mu, -mu);
    u64 c[8];
    u64 v2 = 0ull;
#pragma unroll
    for (int dp = 0; dp < 8; dp++) {
        c[dp] = padd(y[dp], nmu);
        v2 = pfma(c[dp], c[dp], v2);
    }
    float rs = rsqrtf(fmaf(hadd(v2), 0.0625f, 1e-5f));
    u64 rs2 = pk(rs, rs);
    const ulonglong2* g2 = reinterpret_cast<const ulonglong2*>(g);
    const ulonglong2* b2 = reinterpret_cast<const ulonglong2*>(b);
#pragma unroll
    for (int q = 0; q < 4; q++) {
        ulonglong2 gv = g2[q], bv = b2[q];
        o[2*q]   = pfma(pmul(c[2*q],   rs2), gv.x, bv.x);
        o[2*q+1] = pfma(pmul(c[2*q+1], rs2), gv.y, bv.y);
    }
}

__global__ __launch_bounds__(NT, 2)
void ttb_kernel(const float* __restrict__ x,
                const float* __restrict__ Win,  const float* __restrict__ binp,
                const float* __restrict__ Wqkv, const float* __restrict__ bqkv,
                const float* __restrict__ Wo,   const float* __restrict__ bo,
                const float* __restrict__ ln1w, const float* __restrict__ ln1b,
                const float* __restrict__ W1,   const float* __restrict__ b1,
                const float* __restrict__ W2,   const float* __restrict__ b2,
                const float* __restrict__ ln2w, const float* __restrict__ ln2b,
                const float* __restrict__ Wout, const float* __restrict__ bout,
                float* __restrict__ out) {
    extern __shared__ float sm[];
    const int tid = threadIdx.x;

    // ---- stage weights (Q rows pre-scaled by 0.5*log2e; NOTE: % not &) ----
    for (int i = tid; i < 1536; i += NT) {
        float w = Wqkv[i];
        if (((i % 768) >> 4) < 16) w *= QSCALE;   // rows 0..15 of each layer = Q
        sm[OFF_WQKV + i] = w;
    }
    for (int i = tid; i < 96; i += NT) {
        float w = bqkv[i];
        if ((i % 48) < 16) w *= QSCALE;
        sm[OFF_BQKV + i] = w;
    }
    for (int i = tid; i <  512; i += NT) sm[OFF_WO   + i] = Wo[i];
    for (int i = tid; i <   32; i += NT) sm[OFF_BO   + i] = bo[i];
    for (int i = tid; i < 2048; i += NT) sm[OFF_W1   + i] = W1[i];
    for (int i = tid; i <  128; i += NT) sm[OFF_B1   + i] = b1[i];
    for (int i = tid; i < 2048; i += NT) {   // W2 [l][d][o] -> [l][o][d]
        int l = i >> 10, rem = i & 1023, o = rem >> 4, d = rem & 15;
        sm[OFF_W2T + i] = W2[l * 1024 + d * 64 + o];
    }
    for (int i = tid; i <   32; i += NT) sm[OFF_B2   + i] = b2[i];
    for (int i = tid; i <   32; i += NT) sm[OFF_LN1W + i] = ln1w[i];
    for (int i = tid; i <   32; i += NT) sm[OFF_LN1B + i] = ln1b[i];
    for (int i = tid; i <   32; i += NT) sm[OFF_LN2W + i] = ln2w[i];
    for (int i = tid; i <   32; i += NT) sm[OFF_LN2B + i] = ln2b[i];
    for (int i = tid; i <   16; i += NT) sm[OFF_WIN  + i] = Win[i];
    for (int i = tid; i <   16; i += NT) sm[OFF_BIN  + i] = binp[i];
    for (int i = tid; i <   16; i += NT) sm[OFF_WOUT + i] = Wout[i];
    if (tid == 0) sm[OFF_BOUT] = bout[0];

    // ---- stage this block's input pixels ----
    const int n0 = blockIdx.x * S;
    for (int i = tid; i < T * S; i += NT) {
        int t = i >> 4, c = i & 15;
        sm[OFF_XS + t * 17 + c] = x[t * HW + n0 + c];
    }
    __syncthreads();

    const int sl = tid / TPS;
    const int r  = tid % TPS;
    const int n  = n0 + sl;
    const int t0 = 2 * r;                 // tokens t0, t0+1

    // ---- input projection, h as d-pairs ----
    u64 hp0[8], hp1[8];
    {
        float xv0 = sm[OFF_XS + t0 * 17 + sl];
        float xv1 = sm[OFF_XS + (t0 + 1) * 17 + sl];
        u64 xp0 = pk(xv0, xv0), xp1 = pk(xv1, xv1);
        const ulonglong2* w2 = reinterpret_cast<const ulonglong2*>(&sm[OFF_WIN]);
        const ulonglong2* b2 = reinterpret_cast<const ulonglong2*>(&sm[OFF_BIN]);
#pragma unroll
        for (int c = 0; c < 4; c++) {
            ulonglong2 wv = w2[c], bv = b2[c];
            hp0[2*c]   = pfma(xp0, wv.x, bv.x);
            hp0[2*c+1] = pfma(xp0, wv.y, bv.y);
            hp1[2*c]   = pfma(xp1, wv.x, bv.x);
            hp1[2*c+1] = pfma(xp1, wv.y, bv.y);
        }
    }

    float* ksh = &sm[OFF_K + sl * KSEQ];
    float* vsh = &sm[OFF_V + sl * KSEQ];
    float* hstash = &sm[OFF_HS + tid * HS_STRIDE];

#pragma unroll 1
    for (int l = 0; l < NL; l++) {
        const float* wqkv = &sm[OFF_WQKV + l * 768];
        const float* bq   = &sm[OFF_BQKV + l * 48];
        const float* wo   = &sm[OFF_WO   + l * 256];
        const float* bov  = &sm[OFF_BO   + l * 16];
        const float* w1   = &sm[OFF_W1   + l * 1024];
        const float* b1v  = &sm[OFF_B1   + l * 64];
        const float* w2t  = &sm[OFF_W2T  + l * 1024];
        const float* b2v  = &sm[OFF_B2   + l * 16];
        const float* g1w  = &sm[OFF_LN1W + l * 16];
        const float* g1b  = &sm[OFF_LN1B + l * 16];
        const float* g2w  = &sm[OFF_LN2W + l * 16];
        const float* g2b  = &sm[OFF_LN2B + l * 16];

        // ---- Q projection -> per-thread stash (pairs (tok0,tok1) per d) ----
#pragma unroll 4
        for (int o = 0; o < D; o++) {
            float r0, r1;
            dot16x2p(hp0, hp1, wqkv + o * D, bq[o], r0, r1);
            *reinterpret_cast<u64*>(&hstash[2 * o]) = pk(r0, r1);
        }
        // ---- K,V projection -> SoA shared (row = head*4+d, col = s) ----
#pragma unroll 4
        for (int o = 0; o < D; o++) {       // K rows
            float r0, r1;
            dot16x2p(hp0, hp1, wqkv + (D + o) * D, bq[D + o], r0, r1);
            *reinterpret_cast<u64*>(&ksh[o * SROW + t0]) = pk(r0, r1);
        }
#pragma unroll 4
        for (int o = 0; o < D; o++) {       // V rows
            float r0, r1;
            dot16x2p(hp0, hp1, wqkv + (2 * D + o) * D, bq[2 * D + o], r0, r1);
            *reinterpret_cast<u64*>(&vsh[o * SROW + t0]) = pk(r0, r1);
        }
        __syncthreads();

        // ---- attention: K/V loads shared by both tokens ----
        u64 cp0[8], cp1[8];
#pragma unroll
        for (int hd = 0; hd < NH; hd++) {
            // reload q for this head (pairs (tok0,tok1) per d); dup per token
            u64 qp0[4], qp1[4];
#pragma unroll
            for (int d = 0; d < 4; d++) {
                u64 qq = *reinterpret_cast<const u64*>(&hstash[2 * (4 * hd + d)]);
                float qa, qb; unpk(qq, qa, qb);
                qp0[d] = pk(qa, qa);
                qp1[d] = pk(qb, qb);
            }
            const float* kb = ksh + hd * (4 * SROW);
            const float* vb = vsh + hd * (4 * SROW);

            // K pass: logits for BOTH tokens from one set of loads
            u64 lg0[T / 2], lg1[T / 2];
#pragma unroll
            for (int sp = 0; sp < T / 2; sp++) {
                u64 k0 = *reinterpret_cast<const u64*>(kb + 2 * sp);
                u64 k1 = *reinterpret_cast<const u64*>(kb + SROW + 2 * sp);
                u64 k2 = *reinterpret_cast<const u64*>(kb + 2 * SROW + 2 * sp);
                u64 k3 = *reinterpret_cast<const u64*>(kb + 3 * SROW + 2 * sp);
                lg0[sp] = pfma(qp0[0], k0, pfma(qp0[1], k1, pfma(qp0[2], k2, pmul(qp0[3], k3))));
                lg1[sp] = pfma(qp1[0], k0, pfma(qp1[1], k1, pfma(qp1[2], k2, pmul(qp1[3], k3))));
            }
            // softmax in base-2 (Q pre-scaled), no max-subtraction
            u64 s20 = 0ull, s21 = 0ull;
#pragma unroll
            for (int sp = 0; sp < T / 2; sp++) {
                float a, b;
                unpk(lg0[sp], a, b);
                u64 e0 = pk(ex2f(a), ex2f(b));
                lg0[sp] = e0; s20 = padd(s20, e0);
                unpk(lg1[sp], a, b);
                u64 e1 = pk(ex2f(a), ex2f(b));
                lg1[sp] = e1; s21 = padd(s21, e1);
            }
            float inv0 = rcpf(hadd(s20));
            float inv1 = rcpf(hadd(s21));

            // V pass: both tokens' contexts from one set of loads
            u64 a00 = 0ull, a01 = 0ull, a02 = 0ull, a03 = 0ull;
            u64 a10 = 0ull, a11 = 0ull, a12 = 0ull, a13 = 0ull;
#pragma unroll
            for (int sp = 0; sp < T / 2; sp++) {
                u64 v0 = *reinterpret_cast<const u64*>(vb + 2 * sp);
                u64 v1 = *reinterpret_cast<const u64*>(vb + SROW + 2 * sp);
                u64 v2 = *reinterpret_cast<const u64*>(vb + 2 * SROW + 2 * sp);
                u64 v3 = *reinterpret_cast<const u64*>(vb + 3 * SROW + 2 * sp);
                a00 = pfma(lg0[sp], v0, a00);
                a01 = pfma(lg0[sp], v1, a01);
                a02 = pfma(lg0[sp], v2, a02);
                a03 = pfma(lg0[sp], v3, a03);
                a10 = pfma(lg1[sp], v0, a10);
                a11 = pfma(lg1[sp], v1, a11);
                a12 = pfma(lg1[sp], v2, a12);
                a13 = pfma(lg1[sp], v3, a13);
            }
            cp0[2*hd]   = pk(hadd(a00) * inv0, hadd(a01) * inv0);
            cp0[2*hd+1] = pk(hadd(a02) * inv0, hadd(a03) * inv0);
            cp1[2*hd]   = pk(hadd(a10) * inv1, hadd(a11) * inv1);
            cp1[2*hd+1] = pk(hadd(a12) * inv1, hadd(a13) * inv1);
        }

        // ---- Wo projection + residual + LN1 ----
        {
            u64 y0[8], y1[8];
#pragma unroll
            for (int dp = 0; dp < 8; dp++) {
                float a0, a1, b0, b1_;
                dot16x2p(cp0, cp1, wo + (2*dp) * D,     bov[2*dp],     a0, a1);
                dot16x2p(cp0, cp1, wo + (2*dp + 1) * D, bov[2*dp + 1], b0, b1_);
                y0[dp] = padd(hp0[dp], pk(a0, b0));
                y1[dp] = padd(hp1[dp], pk(a1, b1_));
            }
            ln16p(y0, g1w, g1b, hp0);
            ln16p(y1, g1w, g1b, hp1);
        }

        // ---- FFN ----
        {
            u64 f0[8], f1[8];
            const ulonglong2* bb = reinterpret_cast<const ulonglong2*>(b2v);
#pragma unroll
            for (int q = 0; q < 4; q++) {
                ulonglong2 bv = bb[q];
                f0[2*q] = bv.x; f0[2*q+1] = bv.y;
                f1[2*q] = bv.x; f1[2*q+1] = bv.y;
            }
#pragma unroll 4
            for (int o = 0; o < DFF; o++) {
                float u0, u1;
                dot16x2p(hp0, hp1, w1 + o * D, b1v[o], u0, u1);
                u0 = fmaxf(u0, 0.f); u1 = fmaxf(u1, 0.f);
                u64 u0p = pk(u0, u0), u1p = pk(u1, u1);
                const ulonglong2* wr = reinterpret_cast<const ulonglong2*>(w2t + o * D);
#pragma unroll
                for (int c = 0; c < 4; c++) {
                    ulonglong2 wv = wr[c];
                    f0[2*c]   = pfma(u0p, wv.x, f0[2*c]);
                    f0[2*c+1] = pfma(u0p, wv.y, f0[2*c+1]);
                    f1[2*c]   = pfma(u1p, wv.x, f1[2*c]);
                    f1[2*c+1] = pfma(u1p, wv.y, f1[2*c+1]);
                }
            }
            u64 y0[8], y1[8];
#pragma unroll
            for (int dp = 0; dp < 8; dp++) {
                y0[dp] = padd(hp0[dp], f0[dp]);
                y1[dp] = padd(hp1[dp], f1[dp]);
            }
            ln16p(y0, g2w, g2b, hp0);
            ln16p(y1, g2w, g2b, hp1);
        }
        __syncthreads();   // K/V + stash reuse by next layer
    }

    // ---- output projection ----
    {
        const ulonglong2* w2 = reinterpret_cast<const ulonglong2*>(&sm[OFF_WOUT]);
        u64 acc0 = 0ull, acc1 = 0ull;
#pragma unroll
        for (int c = 0; c < 4; c++) {
            ulonglong2 wv = w2[c];
            acc0 = pfma(hp0[2*c],   wv.x, acc0);
            acc0 = pfma(hp0[2*c+1], wv.y, acc0);
            acc1 = pfma(hp1[2*c],   wv.x, acc1);
            acc1 = pfma(hp1[2*c+1], wv.y, acc1);
        }
        float bo_ = sm[OFF_BOUT];
        out[t0 * HW + n]       = hadd(acc0) + bo_;
        out[(t0 + 1) * HW + n] = hadd(acc1) + bo_;
    }
}

extern "C" void kernel_launch(void* const* d_in, const int* in_sizes, int n_in,
                              void* d_out, int out_size) {
    (void)in_sizes; (void)n_in; (void)out_size;
    cudaFuncSetAttribute(ttb_kernel, cudaFuncAttributeMaxDynamicSharedMemorySize,
                         SMEM_BYTES);
    ttb_kernel<<<HW / S, NT, SMEM_BYTES>>>(
        (const float*)d_in[0],  (const float*)d_in[1],  (const float*)d_in[2],
        (const float*)d_in[3],  (const float*)d_in[4],  (const float*)d_in[5],
        (const float*)d_in[6],  (const float*)d_in[7],  (const float*)d_in[8],
        (const float*)d_in[9],  (const float*)d_in[10], (const float*)d_in[11],
        (const float*)d_in[12], (const float*)d_in[13], (const float*)d_in[14],
        (const float*)d_in[15], (const float*)d_in[16],
        (float*)d_out);
}